// round 4
// baseline (speedup 1.0000x reference)
#include <cuda_runtime.h>
#include <cstdint>

// Problem constants
#define BATCH 2
#define SEQ   2048
#define DMODEL 1024
#define NHEAD 16
#define HDIM  64
#define BH    (BATCH*NHEAD)          // 32
#define MROWS (BATCH*SEQ)            // 4096

// Scratch (device globals: allocation-free per harness rules)
__device__ float g_q[BH * SEQ * HDIM];     // [bh][s][hd]
__device__ float g_k[BH * SEQ * HDIM];
__device__ float g_v[BH * SEQ * HDIM];
__device__ float g_ctx[MROWS * DMODEL];    // [b*S+s][d]

// ---------------------------------------------------------------------------
// helpers
// ---------------------------------------------------------------------------
__device__ __forceinline__ uint32_t f2tf32(float x) {
    uint32_t r;
    asm("cvt.rna.tf32.f32 %0, %1;" : "=r"(r) : "f"(x));
    return r;
}

// mma.m16n8k8 tf32, D += A*B (C aliased to D)
__device__ __forceinline__ void mma8(float* d, const uint32_t* a, const uint32_t* b) {
    asm volatile(
        "mma.sync.aligned.m16n8k8.row.col.f32.tf32.tf32.f32 "
        "{%0,%1,%2,%3}, {%4,%5,%6,%7}, {%8,%9}, {%0,%1,%2,%3};\n"
        : "+f"(d[0]), "+f"(d[1]), "+f"(d[2]), "+f"(d[3])
        : "r"(a[0]), "r"(a[1]), "r"(a[2]), "r"(a[3]), "r"(b[0]), "r"(b[1]));
}

// fast 2^y for y <= 0 (clamped at -80), FMA-pipe only, rel err ~3e-6
__device__ __forceinline__ float exp2p(float y) {
    y = fmaxf(y, -80.f);
    int e = __float2int_rn(y);
    float f = y - (float)e;
    float p = 1.3333558e-3f;
    p = fmaf(p, f, 9.6181291e-3f);
    p = fmaf(p, f, 5.5504109e-2f);
    p = fmaf(p, f, 2.4022651e-1f);
    p = fmaf(p, f, 6.9314718e-1f);
    p = fmaf(p, f, 1.0f);
    return __int_as_float(__float_as_int(p) + (e << 23));
}

// ---------------------------------------------------------------------------
// tf32 mma.sync GEMM: C[M,N] = A[M,K] @ B[K,N] + bias.
// Tile 128x128x32, 256 threads, 8 warps (2m x 4n), warp tile 64x32.
// Double-buffered smem, one barrier per k-tile.
// mode 0: write C ; mode 1: scatter into g_q/g_k/g_v (QKV head layout)
// ---------------------------------------------------------------------------
#define GEMM_BUF  (128*36 + 32*132)            // floats per stage: 8832
#define GEMM_SMEM (2 * GEMM_BUF * 4)           // 70,656 B

__device__ __forceinline__ void gemm_stage(
    float* As, float* Bs, const float* A, const float* Bm,
    int m0, int n0, int kt, int K, int N, int tid)
{
    float4 va[4], vb[4];
#pragma unroll
    for (int i = 0; i < 4; i++) {
        int f = tid + i * 256;
        int row = f >> 3, c4 = (f & 7) * 4;
        va[i] = *(const float4*)(A + (size_t)(m0 + row) * K + kt + c4);
    }
#pragma unroll
    for (int i = 0; i < 4; i++) {
        int f = tid + i * 256;
        int kr = f >> 5, nc4 = (f & 31) * 4;
        vb[i] = *(const float4*)(Bm + (size_t)(kt + kr) * N + n0 + nc4);
    }
#pragma unroll
    for (int i = 0; i < 4; i++) {
        int f = tid + i * 256;
        int row = f >> 3, c4 = (f & 7) * 4;
        uint4 u = { f2tf32(va[i].x), f2tf32(va[i].y), f2tf32(va[i].z), f2tf32(va[i].w) };
        *(uint4*)&As[row * 36 + c4] = u;
    }
#pragma unroll
    for (int i = 0; i < 4; i++) {
        int f = tid + i * 256;
        int kr = f >> 5, nc4 = (f & 31) * 4;
        uint4 u = { f2tf32(vb[i].x), f2tf32(vb[i].y), f2tf32(vb[i].z), f2tf32(vb[i].w) };
        *(uint4*)&Bs[kr * 132 + nc4] = u;
    }
}

__global__ __launch_bounds__(256, 2) void gemm_tc(
    const float* __restrict__ A, const float* __restrict__ Bm,
    const float* __restrict__ bias, float* __restrict__ C,
    int M, int N, int K, int mode)
{
    extern __shared__ float sm[];

    const int tid  = threadIdx.x;
    const int wid  = tid >> 5;
    const int lane = tid & 31;
    const int g = lane >> 2, t = lane & 3;
    const int wm = wid >> 2, wn = wid & 3;
    const int m0 = blockIdx.y * 128;
    const int n0 = blockIdx.x * 128;

    float acc[4][4][4];
#pragma unroll
    for (int mt = 0; mt < 4; mt++)
#pragma unroll
        for (int nt = 0; nt < 4; nt++)
#pragma unroll
            for (int j = 0; j < 4; j++) acc[mt][nt][j] = 0.f;

    const int T = K / 32;
    // prologue
    gemm_stage(sm, sm + 128 * 36, A, Bm, m0, n0, 0, K, N, tid);
    __syncthreads();

    for (int tt = 0; tt < T; tt++) {
        float* As = sm + (tt & 1) * GEMM_BUF;
        float* Bs = As + 128 * 36;
        if (tt + 1 < T) {
            float* An = sm + ((tt + 1) & 1) * GEMM_BUF;
            gemm_stage(An, An + 128 * 36, A, Bm, m0, n0, (tt + 1) * 32, K, N, tid);
        }
#pragma unroll
        for (int ks = 0; ks < 4; ks++) {
            uint32_t bb[4][2];
#pragma unroll
            for (int nt = 0; nt < 4; nt++) {
                int col = wn * 32 + nt * 8 + g;
                bb[nt][0] = __float_as_uint(Bs[(ks * 8 + t) * 132 + col]);
                bb[nt][1] = __float_as_uint(Bs[(ks * 8 + t + 4) * 132 + col]);
            }
#pragma unroll
            for (int mt = 0; mt < 4; mt++) {
                int rb = wm * 64 + mt * 16;
                uint32_t aa[4];
                aa[0] = __float_as_uint(As[(rb + g) * 36 + ks * 8 + t]);
                aa[1] = __float_as_uint(As[(rb + g + 8) * 36 + ks * 8 + t]);
                aa[2] = __float_as_uint(As[(rb + g) * 36 + ks * 8 + t + 4]);
                aa[3] = __float_as_uint(As[(rb + g + 8) * 36 + ks * 8 + t + 4]);
#pragma unroll
                for (int nt = 0; nt < 4; nt++)
                    mma8(acc[mt][nt], aa, bb[nt]);
            }
        }
        __syncthreads();
    }

    // epilogue: direct fragment stores (+bias)
#pragma unroll
    for (int mt = 0; mt < 4; mt++) {
        int r0 = m0 + wm * 64 + mt * 16 + g;
        int r1 = r0 + 8;
#pragma unroll
        for (int nt = 0; nt < 4; nt++) {
            int col = n0 + wn * 32 + nt * 8 + 2 * t;
            float2 b2 = *(const float2*)(bias + col);
            float2 v0 = { acc[mt][nt][0] + b2.x, acc[mt][nt][1] + b2.y };
            float2 v1 = { acc[mt][nt][2] + b2.x, acc[mt][nt][3] + b2.y };
            if (mode == 0) {
                *(float2*)(C + (size_t)r0 * N + col) = v0;
                *(float2*)(C + (size_t)r1 * N + col) = v1;
            } else {
                int part = col >> 10;
                int rr   = col & 1023;
                int h    = rr >> 6;
                int hd   = rr & 63;
                float* dst = (part == 0) ? g_q : (part == 1) ? g_k : g_v;
                int b0i = r0 >> 11, s0 = r0 & 2047;
                int b1i = r1 >> 11, s1 = r1 & 2047;
                *(float2*)(dst + ((size_t)(b0i * NHEAD + h) * SEQ + s0) * HDIM + hd) = v0;
                *(float2*)(dst + ((size_t)(b1i * NHEAD + h) * SEQ + s1) * HDIM + hd) = v1;
            }
        }
    }
}

// ---------------------------------------------------------------------------
// Tensor-core causal flash attention (tf32 mma.sync).
// CTA: 256 threads (8 warps), BM=128 query rows (16/warp), BN=64 keys/tile.
// Double-buffered K/V; Q smem reused as per-warp P after frag extraction.
// ---------------------------------------------------------------------------
#define ATT_QSZ (128 * 68)                 // 8704 floats
#define ATT_KVB (64 * 68 * 2)              // K+V per buffer: 8704 floats
#define ATT_SMEM ((ATT_QSZ + 2 * ATT_KVB) * 4)   // 104,448 B

__device__ __forceinline__ void attn_stage_kv(
    float* Kc, float* Vc, const float* kbp, const float* vbp, int kb, int tid)
{
    float4 vk[4], vv[4];
#pragma unroll
    for (int i = 0; i < 4; i++) {
        int f = tid + i * 256;
        int row = f >> 4, c4 = (f & 15) * 4;
        vk[i] = *(const float4*)(kbp + (size_t)(kb + row) * HDIM + c4);
        vv[i] = *(const float4*)(vbp + (size_t)(kb + row) * HDIM + c4);
    }
#pragma unroll
    for (int i = 0; i < 4; i++) {
        int f = tid + i * 256;
        int row = f >> 4, c4 = (f & 15) * 4;
        uint4 uk = { f2tf32(vk[i].x), f2tf32(vk[i].y), f2tf32(vk[i].z), f2tf32(vk[i].w) };
        *(uint4*)&Kc[row * 68 + c4] = uk;
        uint4 uv = { f2tf32(vv[i].x), f2tf32(vv[i].y), f2tf32(vv[i].z), f2tf32(vv[i].w) };
        *(uint4*)&Vc[row * 68 + c4] = uv;
    }
}

__global__ __launch_bounds__(256, 2) void attn_tc()
{
    extern __shared__ float smx[];
    float* Qs = smx;                       // 128x68 ; reused as P per warp
    float* kvb = smx + ATT_QSZ;

    const int tid  = threadIdx.x;
    const int wid  = tid >> 5;
    const int lane = tid & 31;
    const int g = lane >> 2, t = lane & 3;
    const int bh = blockIdx.y;
    const int m0 = ((int)gridDim.x - 1 - (int)blockIdx.x) * 128;  // heavy first

    const float* qb  = g_q + (size_t)bh * SEQ * HDIM;
    const float* kbp = g_k + (size_t)bh * SEQ * HDIM;
    const float* vbp = g_v + (size_t)bh * SEQ * HDIM;

    // stage Q tile (128x64) -> smem (tf32)
#pragma unroll
    for (int i = 0; i < 8; i++) {
        int f = tid + i * 256;
        int row = f >> 4, c4 = (f & 15) * 4;
        float4 v = *(const float4*)(qb + (size_t)(m0 + row) * HDIM + c4);
        uint4 u = { f2tf32(v.x), f2tf32(v.y), f2tf32(v.z), f2tf32(v.w) };
        *(uint4*)&Qs[row * 68 + c4] = u;
    }
    __syncthreads();

    // Q fragments: 8 k-steps x 4 regs (warp rows: wid*16 .. wid*16+15)
    uint32_t qa[8][4];
    {
        int rb = wid * 16;
#pragma unroll
        for (int ks = 0; ks < 8; ks++) {
            qa[ks][0] = __float_as_uint(Qs[(rb + g) * 68 + ks * 8 + t]);
            qa[ks][1] = __float_as_uint(Qs[(rb + g + 8) * 68 + ks * 8 + t]);
            qa[ks][2] = __float_as_uint(Qs[(rb + g) * 68 + ks * 8 + t + 4]);
            qa[ks][3] = __float_as_uint(Qs[(rb + g + 8) * 68 + ks * 8 + t + 4]);
        }
    }
    __syncthreads();   // Qs fully consumed -> safe to reuse as P

    float o[8][4];
#pragma unroll
    for (int nt = 0; nt < 8; nt++)
#pragma unroll
        for (int j = 0; j < 4; j++) o[nt][j] = 0.f;
    float mlo = -1e30f, mhi = -1e30f, llo = 0.f, lhi = 0.f;

    const float SC = 0.125f * 1.44269504f;   // score scale, base-2 domain
    const int ntile = m0 / 64 + 2;           // keys up to m0+127

    // prologue: tile 0 -> buffer 0
    attn_stage_kv(kvb, kvb + 64 * 68, kbp, vbp, 0, tid);
    __syncthreads();

    for (int tt = 0; tt < ntile; tt++) {
        const int kb = tt * 64;
        float* Kc = kvb + (tt & 1) * ATT_KVB;
        float* Vc = Kc + 64 * 68;
        if (tt + 1 < ntile) {
            float* Kn = kvb + ((tt + 1) & 1) * ATT_KVB;
            attn_stage_kv(Kn, Kn + 64 * 68, kbp, vbp, kb + 64, tid);
        }

        // S = Q @ K^T  (warp: 16 x 64)
        float s[8][4];
#pragma unroll
        for (int nt = 0; nt < 8; nt++)
#pragma unroll
            for (int j = 0; j < 4; j++) s[nt][j] = 0.f;
#pragma unroll
        for (int ks = 0; ks < 8; ks++) {
#pragma unroll
            for (int nt = 0; nt < 8; nt++) {
                uint32_t bb[2];
                bb[0] = __float_as_uint(Kc[(nt * 8 + g) * 68 + ks * 8 + t]);
                bb[1] = __float_as_uint(Kc[(nt * 8 + g) * 68 + ks * 8 + t + 4]);
                mma8(s[nt], qa[ks], bb);
            }
        }

        // scale (+ causal mask near diagonal)
        const int rlo = m0 + wid * 16 + g;
        const int rhi = rlo + 8;
        if (kb + 63 > m0 + wid * 16) {
#pragma unroll
            for (int nt = 0; nt < 8; nt++) {
                int c0 = kb + nt * 8 + 2 * t;
                s[nt][0] = (c0     > rlo) ? -1e30f : s[nt][0] * SC;
                s[nt][1] = (c0 + 1 > rlo) ? -1e30f : s[nt][1] * SC;
                s[nt][2] = (c0     > rhi) ? -1e30f : s[nt][2] * SC;
                s[nt][3] = (c0 + 1 > rhi) ? -1e30f : s[nt][3] * SC;
            }
        } else {
#pragma unroll
            for (int nt = 0; nt < 8; nt++)
#pragma unroll
                for (int j = 0; j < 4; j++) s[nt][j] *= SC;
        }

        // row max (quad reduction)
        float tlo = -1e30f, thi = -1e30f;
#pragma unroll
        for (int nt = 0; nt < 8; nt++) {
            tlo = fmaxf(tlo, fmaxf(s[nt][0], s[nt][1]));
            thi = fmaxf(thi, fmaxf(s[nt][2], s[nt][3]));
        }
        tlo = fmaxf(tlo, __shfl_xor_sync(0xffffffff, tlo, 1));
        tlo = fmaxf(tlo, __shfl_xor_sync(0xffffffff, tlo, 2));
        thi = fmaxf(thi, __shfl_xor_sync(0xffffffff, thi, 1));
        thi = fmaxf(thi, __shfl_xor_sync(0xffffffff, thi, 2));

        float nmlo = fmaxf(mlo, tlo), nmhi = fmaxf(mhi, thi);
        float alo = exp2p(mlo - nmlo), ahi = exp2p(mhi - nmhi);
        mlo = nmlo; mhi = nmhi;

        // p = 2^(s-m), partial sums
        float slo = 0.f, shi = 0.f;
#pragma unroll
        for (int nt = 0; nt < 8; nt++) {
            s[nt][0] = exp2p(s[nt][0] - mlo);
            s[nt][1] = exp2p(s[nt][1] - mlo);
            s[nt][2] = exp2p(s[nt][2] - mhi);
            s[nt][3] = exp2p(s[nt][3] - mhi);
            slo += s[nt][0] + s[nt][1];
            shi += s[nt][2] + s[nt][3];
        }
        slo += __shfl_xor_sync(0xffffffff, slo, 1);
        slo += __shfl_xor_sync(0xffffffff, slo, 2);
        shi += __shfl_xor_sync(0xffffffff, shi, 1);
        shi += __shfl_xor_sync(0xffffffff, shi, 2);
        llo = llo * alo + slo;
        lhi = lhi * ahi + shi;

        // rescale O
#pragma unroll
        for (int nt = 0; nt < 8; nt++) {
            o[nt][0] *= alo; o[nt][1] *= alo;
            o[nt][2] *= ahi; o[nt][3] *= ahi;
        }

        // P -> smem (warp-private 16x68 region inside Qs), tf32
        float* Ps = Qs + wid * (16 * 68);
#pragma unroll
        for (int nt = 0; nt < 8; nt++) {
            int c = nt * 8 + 2 * t;
            uint2 plo = { f2tf32(s[nt][0]), f2tf32(s[nt][1]) };
            uint2 phi = { f2tf32(s[nt][2]), f2tf32(s[nt][3]) };
            *(uint2*)&Ps[g * 68 + c]       = plo;
            *(uint2*)&Ps[(g + 8) * 68 + c] = phi;
        }
        __syncwarp();

        // O += P @ V
#pragma unroll
        for (int ks = 0; ks < 8; ks++) {
            uint32_t aa[4];
            aa[0] = __float_as_uint(Ps[g * 68 + ks * 8 + t]);
            aa[1] = __float_as_uint(Ps[(g + 8) * 68 + ks * 8 + t]);
            aa[2] = __float_as_uint(Ps[g * 68 + ks * 8 + t + 4]);
            aa[3] = __float_as_uint(Ps[(g + 8) * 68 + ks * 8 + t + 4]);
#pragma unroll
            for (int nt = 0; nt < 8; nt++) {
                uint32_t bb[2];
                bb[0] = __float_as_uint(Vc[(ks * 8 + t) * 68 + nt * 8 + g]);
                bb[1] = __float_as_uint(Vc[(ks * 8 + t + 4) * 68 + nt * 8 + g]);
                mma8(o[nt], aa, bb);
            }
        }
        __syncthreads();
    }

    // epilogue: O /= l, write to ctx
    const float ilo = 1.f / llo, ihi = 1.f / lhi;
    const int rlo = m0 + wid * 16 + g;
    const int rhi = rlo + 8;
    const int bidx = bh >> 4, h = bh & 15;
    float* clo = g_ctx + ((size_t)(bidx * SEQ + rlo)) * DMODEL + h * HDIM;
    float* chi = g_ctx + ((size_t)(bidx * SEQ + rhi)) * DMODEL + h * HDIM;
#pragma unroll
    for (int nt = 0; nt < 8; nt++) {
        int c = nt * 8 + 2 * t;
        float2 v0 = { o[nt][0] * ilo, o[nt][1] * ilo };
        float2 v1 = { o[nt][2] * ihi, o[nt][3] * ihi };
        *(float2*)(clo + c) = v0;
        *(float2*)(chi + c) = v1;
    }
}

// ---------------------------------------------------------------------------
extern "C" void kernel_launch(void* const* d_in, const int* in_sizes, int n_in,
                              void* d_out, int out_size)
{
    const float* x      = (const float*)d_in[0];   // [B,S,D]
    const float* w_qkv  = (const float*)d_in[1];   // [D, 3D]
    const float* b_qkv  = (const float*)d_in[2];   // [3D]
    const float* w_proj = (const float*)d_in[3];   // [D, D]
    const float* b_proj = (const float*)d_in[4];   // [D]
    float* out = (float*)d_out;                    // [B,S,D]

    float* ctx;
    cudaGetSymbolAddress((void**)&ctx, g_ctx);

    cudaFuncSetAttribute(gemm_tc, cudaFuncAttributeMaxDynamicSharedMemorySize, GEMM_SMEM);
    cudaFuncSetAttribute(attn_tc, cudaFuncAttributeMaxDynamicSharedMemorySize, ATT_SMEM);

    // 1) QKV projection -> g_q/g_k/g_v
    {
        dim3 grid(3 * DMODEL / 128, MROWS / 128);  // (24, 32)
        gemm_tc<<<grid, 256, GEMM_SMEM>>>(x, w_qkv, b_qkv, nullptr,
                                          MROWS, 3 * DMODEL, DMODEL, /*mode=*/1);
    }
    // 2) causal attention -> g_ctx
    {
        dim3 grid(SEQ / 128, BH);                  // (16, 32)
        attn_tc<<<grid, 256, ATT_SMEM>>>();
    }
    // 3) output projection -> d_out
    {
        dim3 grid(DMODEL / 128, MROWS / 128);      // (8, 32)
        gemm_tc<<<grid, 256, GEMM_SMEM>>>(ctx, w_proj, b_proj, out,
                                          MROWS, DMODEL, DMODEL, /*mode=*/0);
    }
    (void)in_sizes; (void)n_in; (void)out_size;
}

// round 5
// speedup vs baseline: 1.0007x; 1.0007x over previous
#include <cuda_runtime.h>
#include <cstdint>

// Problem constants
#define BATCH 2
#define SEQ   2048
#define DMODEL 1024
#define NHEAD 16
#define HDIM  64
#define BH    (BATCH*NHEAD)          // 32
#define MROWS (BATCH*SEQ)            // 4096

// Scratch (device globals: allocation-free per harness rules)
__device__ float g_q[BH * SEQ * HDIM];     // [bh][s][hd]
__device__ float g_k[BH * SEQ * HDIM];
__device__ float g_v[BH * SEQ * HDIM];
__device__ float g_ctx[MROWS * DMODEL];    // [b*S+s][d]

// ---------------------------------------------------------------------------
// helpers
// ---------------------------------------------------------------------------
__device__ __forceinline__ uint32_t f2tf32(float x) {
    uint32_t r;
    asm("cvt.rna.tf32.f32 %0, %1;" : "=r"(r) : "f"(x));
    return r;
}
__device__ __forceinline__ float tf(float x) {       // tf32 bits as float
    return __uint_as_float(f2tf32(x));
}

// mma.m16n8k8 tf32, D += A*B (C aliased to D)
__device__ __forceinline__ void mma8(float* d, const uint32_t* a, const uint32_t* b) {
    asm volatile(
        "mma.sync.aligned.m16n8k8.row.col.f32.tf32.tf32.f32 "
        "{%0,%1,%2,%3}, {%4,%5,%6,%7}, {%8,%9}, {%0,%1,%2,%3};\n"
        : "+f"(d[0]), "+f"(d[1]), "+f"(d[2]), "+f"(d[3])
        : "r"(a[0]), "r"(a[1]), "r"(a[2]), "r"(a[3]), "r"(b[0]), "r"(b[1]));
}

// fast 2^y for y <= 0 (clamped at -80), FMA-pipe only, rel err ~3e-6
__device__ __forceinline__ float exp2p(float y) {
    y = fmaxf(y, -80.f);
    int e = __float2int_rn(y);
    float f = y - (float)e;
    float p = 1.3333558e-3f;
    p = fmaf(p, f, 9.6181291e-3f);
    p = fmaf(p, f, 5.5504109e-2f);
    p = fmaf(p, f, 2.4022651e-1f);
    p = fmaf(p, f, 6.9314718e-1f);
    p = fmaf(p, f, 1.0f);
    return __int_as_float(__float_as_int(p) + (e << 23));
}

// ===========================================================================
// Fragment-layout smem conventions (all float4-granular, XOR-swizzled):
//  A-type (M rows x K cols): slot f4 = row16*(Kc/8*32) + ks*32 + g*4 + ((t^g^ks)&3)
//    components: {(g,t),(g+8,t),(g,t+4),(g+8,t+4)}  [r8 + 2*t4]
//  B-type (K rows x N cols): slot f4 = ks*(Nc/16*32) + pair*32 + g*4 + ((t^g^pair)&3)
//    components: {(t,2p*8+g),(t+4,2p*8+g),(t,(2p+1)*8+g),(t+4,(2p+1)*8+g)} [t4 + 2*nt2]
// One LDS.128 per fragment pair; staging scatters with 4x STS.32.
// ===========================================================================

// ---------------------------------------------------------------------------
// tf32 mma.sync GEMM: C[M,N] = A[M,K] @ B[K,N] + bias.
// Tile 128x128x32, 256 threads, 8 warps (2m x 4n), warp tile 64x32.
// Double-buffered frag-layout smem, one barrier per k-tile.
// ---------------------------------------------------------------------------
#define GEMM_STG  2048                        // float4 per stage (A 1024 + B 1024)
#define GEMM_SMEM (2 * GEMM_STG * 16)         // 65,536 B

__device__ __forceinline__ void gemm_stage(
    float* As, float* Bs, const float* __restrict__ A, const float* __restrict__ Bm,
    int m0, int n0, int kt, int K, int N, int tid)
{
    float4 va[4], vb[4];
#pragma unroll
    for (int i = 0; i < 4; i++) {
        int f = tid + i * 256;
        int row = f >> 3, c0 = (f & 7) * 4;
        va[i] = *(const float4*)(A + (size_t)(m0 + row) * K + kt + c0);
    }
#pragma unroll
    for (int i = 0; i < 4; i++) {
        int f = tid + i * 256;
        int kr = f >> 5, c0 = (f & 31) * 4;
        vb[i] = *(const float4*)(Bm + (size_t)(kt + kr) * N + n0 + c0);
    }
#pragma unroll
    for (int i = 0; i < 4; i++) {
        int f = tid + i * 256;
        int row = f >> 3, c0 = (f & 7) * 4;
        int row16 = row >> 4, g = row & 7, r8 = (row >> 3) & 1;
        int ks = c0 >> 3, t4 = (c0 >> 2) & 1;
        int comp = r8 + 2 * t4;
        int base = row16 * 128 + ks * 32 + g * 4;
        float v[4] = { tf(va[i].x), tf(va[i].y), tf(va[i].z), tf(va[i].w) };
#pragma unroll
        for (int j = 0; j < 4; j++)
            As[(base + ((j ^ g ^ ks) & 3)) * 4 + comp] = v[j];
    }
#pragma unroll
    for (int i = 0; i < 4; i++) {
        int f = tid + i * 256;
        int kr = f >> 5, c0 = (f & 31) * 4;
        int ks = kr >> 3, tt = kr & 3, tt4 = (kr >> 2) & 1;
        int pair = c0 >> 4, nt2 = (c0 >> 3) & 1, gb = c0 & 7;
        int comp = tt4 + 2 * nt2;
        int base = ks * 256 + pair * 32;
        float v[4] = { tf(vb[i].x), tf(vb[i].y), tf(vb[i].z), tf(vb[i].w) };
#pragma unroll
        for (int j = 0; j < 4; j++) {
            int gg = gb + j;
            Bs[(base + gg * 4 + ((tt ^ gg ^ pair) & 3)) * 4 + comp] = v[j];
        }
    }
}

__global__ __launch_bounds__(256, 2) void gemm_tc(
    const float* __restrict__ A, const float* __restrict__ Bm,
    const float* __restrict__ bias, float* __restrict__ C,
    int M, int N, int K, int mode)
{
    extern __shared__ float sm[];

    const int tid  = threadIdx.x;
    const int wid  = tid >> 5;
    const int lane = tid & 31;
    const int g = lane >> 2, t = lane & 3;
    const int wm = wid >> 2, wn = wid & 3;
    const int m0 = blockIdx.y * 128;
    const int n0 = blockIdx.x * 128;

    float acc[4][4][4];
#pragma unroll
    for (int mt = 0; mt < 4; mt++)
#pragma unroll
        for (int nt = 0; nt < 4; nt++)
#pragma unroll
            for (int j = 0; j < 4; j++) acc[mt][nt][j] = 0.f;

    const int T = K / 32;
    gemm_stage(sm, sm + 1024 * 4, A, Bm, m0, n0, 0, K, N, tid);
    __syncthreads();

    for (int tt = 0; tt < T; tt++) {
        float* As = sm + (tt & 1) * (GEMM_STG * 4);
        float* Bs = As + 1024 * 4;
        if (tt + 1 < T) {
            float* An = sm + ((tt + 1) & 1) * (GEMM_STG * 4);
            gemm_stage(An, An + 1024 * 4, A, Bm, m0, n0, (tt + 1) * 32, K, N, tid);
        }
        const float4* Af = (const float4*)As;
        const float4* Bf = (const float4*)Bs;
#pragma unroll
        for (int ks = 0; ks < 4; ks++) {
            uint32_t bb[4][2];
#pragma unroll
            for (int p = 0; p < 2; p++) {
                int pr = wn * 2 + p;
                float4 b4 = Bf[ks * 256 + pr * 32 + g * 4 + ((t ^ g ^ pr) & 3)];
                bb[2*p][0]   = __float_as_uint(b4.x);
                bb[2*p][1]   = __float_as_uint(b4.y);
                bb[2*p+1][0] = __float_as_uint(b4.z);
                bb[2*p+1][1] = __float_as_uint(b4.w);
            }
#pragma unroll
            for (int mt = 0; mt < 4; mt++) {
                float4 a4 = Af[(wm * 4 + mt) * 128 + ks * 32 + g * 4 + ((t ^ g ^ ks) & 3)];
                uint32_t aa[4] = { __float_as_uint(a4.x), __float_as_uint(a4.y),
                                   __float_as_uint(a4.z), __float_as_uint(a4.w) };
#pragma unroll
                for (int nt = 0; nt < 4; nt++)
                    mma8(acc[mt][nt], aa, bb[nt]);
            }
        }
        __syncthreads();
    }

    // epilogue: direct fragment stores (+bias)
#pragma unroll
    for (int mt = 0; mt < 4; mt++) {
        int r0 = m0 + wm * 64 + mt * 16 + g;
        int r1 = r0 + 8;
#pragma unroll
        for (int nt = 0; nt < 4; nt++) {
            int col = n0 + wn * 32 + nt * 8 + 2 * t;
            float2 b2 = *(const float2*)(bias + col);
            float2 v0 = { acc[mt][nt][0] + b2.x, acc[mt][nt][1] + b2.y };
            float2 v1 = { acc[mt][nt][2] + b2.x, acc[mt][nt][3] + b2.y };
            if (mode == 0) {
                *(float2*)(C + (size_t)r0 * N + col) = v0;
                *(float2*)(C + (size_t)r1 * N + col) = v1;
            } else {
                int part = col >> 10;
                int rr   = col & 1023;
                int h    = rr >> 6;
                int hd   = rr & 63;
                float* dst = (part == 0) ? g_q : (part == 1) ? g_k : g_v;
                int b0i = r0 >> 11, s0 = r0 & 2047;
                int b1i = r1 >> 11, s1 = r1 & 2047;
                *(float2*)(dst + ((size_t)(b0i * NHEAD + h) * SEQ + s0) * HDIM + hd) = v0;
                *(float2*)(dst + ((size_t)(b1i * NHEAD + h) * SEQ + s1) * HDIM + hd) = v1;
            }
        }
    }
}

// ---------------------------------------------------------------------------
// Tensor-core causal flash attention (tf32 mma.sync), frag-layout smem.
// CTA: 256 threads (8 warps), BM=128 (16 rows/warp), BN=64 keys/tile.
// smem f4 map: [0,2048) Q-frags (reused as per-warp P-frags),
//              [2048 + s*2048, +1024) K stage s, +1024 V stage s.
// ---------------------------------------------------------------------------
#define ATT_SMEM (6144 * 16)     // 98,304 B

__device__ __forceinline__ void attn_stage_kv(
    float* Kd, float* Vd,
    const float* __restrict__ kbp, const float* __restrict__ vbp, int kb, int tid)
{
    float4 k4[4], v4[4];
#pragma unroll
    for (int i = 0; i < 4; i++) {
        int f = tid + i * 256;
        int row = f >> 4, c0 = (f & 15) * 4;
        k4[i] = *(const float4*)(kbp + (size_t)(kb + row) * HDIM + c0);
        v4[i] = *(const float4*)(vbp + (size_t)(kb + row) * HDIM + c0);
    }
#pragma unroll
    for (int i = 0; i < 4; i++) {
        int f = tid + i * 256;
        int row = f >> 4, c0 = (f & 15) * 4;
        // K as B-operand of S=Q@K^T: k-dim = hd, n-dim = key(row)
        {
            int ks = c0 >> 3, tt4 = (c0 >> 2) & 1;
            int pair = row >> 4, nt2 = (row >> 3) & 1, g = row & 7;
            int comp = tt4 + 2 * nt2;
            int base = ks * 128 + pair * 32 + g * 4;
            float v[4] = { tf(k4[i].x), tf(k4[i].y), tf(k4[i].z), tf(k4[i].w) };
#pragma unroll
            for (int j = 0; j < 4; j++)
                Kd[(base + ((j ^ g ^ pair) & 3)) * 4 + comp] = v[j];
        }
        // V as B-operand of O=P@V: k-dim = key(row), n-dim = hd
        {
            int ks = row >> 3, tt = row & 3, tt4 = (row >> 2) & 1;
            int pair = c0 >> 4, nt2 = (c0 >> 3) & 1, gb = c0 & 7;
            int comp = tt4 + 2 * nt2;
            int base = ks * 128 + pair * 32;
            float v[4] = { tf(v4[i].x), tf(v4[i].y), tf(v4[i].z), tf(v4[i].w) };
#pragma unroll
            for (int j = 0; j < 4; j++) {
                int gg = gb + j;
                Vd[(base + gg * 4 + ((tt ^ gg ^ pair) & 3)) * 4 + comp] = v[j];
            }
        }
    }
}

__global__ __launch_bounds__(256, 2) void attn_tc()
{
    extern __shared__ float smx[];

    const int tid  = threadIdx.x;
    const int wid  = tid >> 5;
    const int lane = tid & 31;
    const int g = lane >> 2, t = lane & 3;
    const int bh = blockIdx.y;
    const int m0 = ((int)gridDim.x - 1 - (int)blockIdx.x) * 128;  // heavy first

    const float* qb  = g_q + (size_t)bh * SEQ * HDIM;
    const float* kbp = g_k + (size_t)bh * SEQ * HDIM;
    const float* vbp = g_v + (size_t)bh * SEQ * HDIM;

    // stage Q tile (128x64) into A-frag layout (2048 f4)
#pragma unroll
    for (int i = 0; i < 8; i++) {
        int f = tid + i * 256;
        int row = f >> 4, c0 = (f & 15) * 4;
        float4 q4 = *(const float4*)(qb + (size_t)(m0 + row) * HDIM + c0);
        int row16 = row >> 4, gq = row & 7, r8 = (row >> 3) & 1;
        int ks = c0 >> 3, t4 = (c0 >> 2) & 1;
        int comp = r8 + 2 * t4;
        int base = row16 * 256 + ks * 32 + gq * 4;
        float v[4] = { tf(q4.x), tf(q4.y), tf(q4.z), tf(q4.w) };
#pragma unroll
        for (int j = 0; j < 4; j++)
            smx[(base + ((j ^ gq ^ ks) & 3)) * 4 + comp] = v[j];
    }
    __syncthreads();

    // Q fragments: 8 k-steps x 4 regs (warp's own 256-f4 block)
    uint32_t qa[8][4];
    {
        const float4* Qf = (const float4*)smx;
#pragma unroll
        for (int ks = 0; ks < 8; ks++) {
            float4 a4 = Qf[wid * 256 + ks * 32 + g * 4 + ((t ^ g ^ ks) & 3)];
            qa[ks][0] = __float_as_uint(a4.x);
            qa[ks][1] = __float_as_uint(a4.y);
            qa[ks][2] = __float_as_uint(a4.z);
            qa[ks][3] = __float_as_uint(a4.w);
        }
    }
    // Q block is warp-private; it becomes this warp's P region (no CTA barrier needed)

    float o[8][4];
#pragma unroll
    for (int nt = 0; nt < 8; nt++)
#pragma unroll
        for (int j = 0; j < 4; j++) o[nt][j] = 0.f;
    float mlo = -1e30f, mhi = -1e30f, llo = 0.f, lhi = 0.f;

    const float SC = 0.125f * 1.44269504f;   // score scale, base-2 domain
    const int ntile = m0 / 64 + 2;           // keys up to m0+127

    // prologue: tile 0 -> buffer 0
    attn_stage_kv(smx + 2048 * 4, smx + 3072 * 4, kbp, vbp, 0, tid);
    __syncthreads();

    for (int tt = 0; tt < ntile; tt++) {
        const int kb = tt * 64;
        float* Kc = smx + (2048 + (tt & 1) * 2048) * 4;
        float* Vc = Kc + 1024 * 4;
        if (tt + 1 < ntile) {
            float* Kn = smx + (2048 + ((tt + 1) & 1) * 2048) * 4;
            attn_stage_kv(Kn, Kn + 1024 * 4, kbp, vbp, kb + 64, tid);
        }
        const float4* Kf = (const float4*)Kc;
        const float4* Vf = (const float4*)Vc;

        // S = Q @ K^T  (warp: 16 x 64)
        float s[8][4];
#pragma unroll
        for (int nt = 0; nt < 8; nt++)
#pragma unroll
            for (int j = 0; j < 4; j++) s[nt][j] = 0.f;
#pragma unroll
        for (int ks = 0; ks < 8; ks++) {
            uint32_t bb[8][2];
#pragma unroll
            for (int p = 0; p < 4; p++) {
                float4 b4 = Kf[ks * 128 + p * 32 + g * 4 + ((t ^ g ^ p) & 3)];
                bb[2*p][0]   = __float_as_uint(b4.x);
                bb[2*p][1]   = __float_as_uint(b4.y);
                bb[2*p+1][0] = __float_as_uint(b4.z);
                bb[2*p+1][1] = __float_as_uint(b4.w);
            }
#pragma unroll
            for (int nt = 0; nt < 8; nt++)
                mma8(s[nt], qa[ks], bb[nt]);
        }

        // scale (+ causal mask near diagonal)
        const int rlo = m0 + wid * 16 + g;
        const int rhi = rlo + 8;
        if (kb + 63 > m0 + wid * 16) {
#pragma unroll
            for (int nt = 0; nt < 8; nt++) {
                int c0 = kb + nt * 8 + 2 * t;
                s[nt][0] = (c0     > rlo) ? -1e30f : s[nt][0] * SC;
                s[nt][1] = (c0 + 1 > rlo) ? -1e30f : s[nt][1] * SC;
                s[nt][2] = (c0     > rhi) ? -1e30f : s[nt][2] * SC;
                s[nt][3] = (c0 + 1 > rhi) ? -1e30f : s[nt][3] * SC;
            }
        } else {
#pragma unroll
            for (int nt = 0; nt < 8; nt++)
#pragma unroll
                for (int j = 0; j < 4; j++) s[nt][j] *= SC;
        }

        // row max (quad reduction)
        float tlo = -1e30f, thi = -1e30f;
#pragma unroll
        for (int nt = 0; nt < 8; nt++) {
            tlo = fmaxf(tlo, fmaxf(s[nt][0], s[nt][1]));
            thi = fmaxf(thi, fmaxf(s[nt][2], s[nt][3]));
        }
        tlo = fmaxf(tlo, __shfl_xor_sync(0xffffffff, tlo, 1));
        tlo = fmaxf(tlo, __shfl_xor_sync(0xffffffff, tlo, 2));
        thi = fmaxf(thi, __shfl_xor_sync(0xffffffff, thi, 1));
        thi = fmaxf(thi, __shfl_xor_sync(0xffffffff, thi, 2));

        float nmlo = fmaxf(mlo, tlo), nmhi = fmaxf(mhi, thi);
        float alo = exp2p(mlo - nmlo), ahi = exp2p(mhi - nmhi);
        mlo = nmlo; mhi = nmhi;

        // p = 2^(s-m), partial sums
        float slo = 0.f, shi = 0.f;
#pragma unroll
        for (int nt = 0; nt < 8; nt++) {
            s[nt][0] = exp2p(s[nt][0] - mlo);
            s[nt][1] = exp2p(s[nt][1] - mlo);
            s[nt][2] = exp2p(s[nt][2] - mhi);
            s[nt][3] = exp2p(s[nt][3] - mhi);
            slo += s[nt][0] + s[nt][1];
            shi += s[nt][2] + s[nt][3];
        }
        slo += __shfl_xor_sync(0xffffffff, slo, 1);
        slo += __shfl_xor_sync(0xffffffff, slo, 2);
        shi += __shfl_xor_sync(0xffffffff, shi, 1);
        shi += __shfl_xor_sync(0xffffffff, shi, 2);
        llo = llo * alo + slo;
        lhi = lhi * ahi + shi;

        // rescale O
#pragma unroll
        for (int nt = 0; nt < 8; nt++) {
            o[nt][0] *= alo; o[nt][1] *= alo;
            o[nt][2] *= ahi; o[nt][3] *= ahi;
        }

        // P -> warp-private A-frag layout (reusing the warp's Q block)
        {
            const int c0 = 2 * (t >> 1);
#pragma unroll
            for (int nt = 0; nt < 8; nt++) {
                int sA = wid * 256 + nt * 32 + g * 4 + ((((2 * t) & 3) ^ g ^ nt) & 3);
                int sB = wid * 256 + nt * 32 + g * 4 + ((((2 * t + 1) & 3) ^ g ^ nt) & 3);
                float2 vA = { tf(s[nt][0]), tf(s[nt][2]) };
                float2 vB = { tf(s[nt][1]), tf(s[nt][3]) };
                *(float2*)(smx + sA * 4 + c0) = vA;
                *(float2*)(smx + sB * 4 + c0) = vB;
            }
        }
        __syncwarp();

        // O += P @ V
        {
            const float4* Pf = (const float4*)smx;
#pragma unroll
            for (int ks = 0; ks < 8; ks++) {
                float4 a4 = Pf[wid * 256 + ks * 32 + g * 4 + ((t ^ g ^ ks) & 3)];
                uint32_t aa[4] = { __float_as_uint(a4.x), __float_as_uint(a4.y),
                                   __float_as_uint(a4.z), __float_as_uint(a4.w) };
#pragma unroll
                for (int p = 0; p < 4; p++) {
                    float4 b4 = Vf[ks * 128 + p * 32 + g * 4 + ((t ^ g ^ p) & 3)];
                    uint32_t b0[2] = { __float_as_uint(b4.x), __float_as_uint(b4.y) };
                    uint32_t b1[2] = { __float_as_uint(b4.z), __float_as_uint(b4.w) };
                    mma8(o[2*p],   aa, b0);
                    mma8(o[2*p+1], aa, b1);
                }
            }
        }
        __syncwarp();
        __syncthreads();   // KV buffer handoff
    }

    // epilogue: O /= l, write to ctx
    const float ilo = 1.f / llo, ihi = 1.f / lhi;
    const int rlo = m0 + wid * 16 + g;
    const int rhi = rlo + 8;
    const int bidx = bh >> 4, h = bh & 15;
    float* clo = g_ctx + ((size_t)(bidx * SEQ + rlo)) * DMODEL + h * HDIM;
    float* chi = g_ctx + ((size_t)(bidx * SEQ + rhi)) * DMODEL + h * HDIM;
#pragma unroll
    for (int nt = 0; nt < 8; nt++) {
        int c = nt * 8 + 2 * t;
        float2 v0 = { o[nt][0] * ilo, o[nt][1] * ilo };
        float2 v1 = { o[nt][2] * ihi, o[nt][3] * ihi };
        *(float2*)(clo + c) = v0;
        *(float2*)(chi + c) = v1;
    }
}

// ---------------------------------------------------------------------------
extern "C" void kernel_launch(void* const* d_in, const int* in_sizes, int n_in,
                              void* d_out, int out_size)
{
    const float* x      = (const float*)d_in[0];   // [B,S,D]
    const float* w_qkv  = (const float*)d_in[1];   // [D, 3D]
    const float* b_qkv  = (const float*)d_in[2];   // [3D]
    const float* w_proj = (const float*)d_in[3];   // [D, D]
    const float* b_proj = (const float*)d_in[4];   // [D]
    float* out = (float*)d_out;                    // [B,S,D]

    float* ctx;
    cudaGetSymbolAddress((void**)&ctx, g_ctx);

    cudaFuncSetAttribute(gemm_tc, cudaFuncAttributeMaxDynamicSharedMemorySize, GEMM_SMEM);
    cudaFuncSetAttribute(attn_tc, cudaFuncAttributeMaxDynamicSharedMemorySize, ATT_SMEM);

    // 1) QKV projection -> g_q/g_k/g_v
    {
        dim3 grid(3 * DMODEL / 128, MROWS / 128);  // (24, 32)
        gemm_tc<<<grid, 256, GEMM_SMEM>>>(x, w_qkv, b_qkv, nullptr,
                                          MROWS, 3 * DMODEL, DMODEL, /*mode=*/1);
    }
    // 2) causal attention -> g_ctx
    {
        dim3 grid(SEQ / 128, BH);                  // (16, 32)
        attn_tc<<<grid, 256, ATT_SMEM>>>();
    }
    // 3) output projection -> d_out
    {
        dim3 grid(DMODEL / 128, MROWS / 128);      // (8, 32)
        gemm_tc<<<grid, 256, GEMM_SMEM>>>(ctx, w_proj, b_proj, out,
                                          MROWS, DMODEL, DMODEL, /*mode=*/0);
    }
    (void)in_sizes; (void)n_in; (void)out_size;
}